// round 1
// baseline (speedup 1.0000x reference)
#include <cuda_runtime.h>
#include <math.h>
#include <stdint.h>

// Problem constants
#define BB 32
#define TT 512
#define DD 512
#define UU 1024
#define NC 4096   // 4*U packed gate columns, layout [unit][gate] with gate order f,i,g,o

// -------- device scratch (allocation-free rule: __device__ globals) --------
__device__ float g_Whp[1024 * 4096];          // [k][u*4+g]   recurrent weights, 16 MB
__device__ float g_Wxp[512 * 4096];           // [d][u*4+g]   input weights, 8 MB
__device__ float g_bp[4096];                  // packed biases [u*4+g]
__device__ float g_zx[(size_t)TT * BB * NC];  // [t][b][u*4+g]  precomputed x-part (+bias), 256 MB
__device__ float g_h[2][BB * UU];             // ping-pong hidden state [b][u]
__device__ float g_c[BB * UU];                // cell state [b][u]

// -------- f32x2 helpers (Blackwell packed fp32: 2x FFMA throughput) --------
__device__ __forceinline__ void fma2(unsigned long long& acc, unsigned long long a,
                                     unsigned long long b) {
    asm("fma.rn.f32x2 %0, %1, %2, %3;" : "=l"(acc) : "l"(a), "l"(b), "l"(acc));
}
__device__ __forceinline__ unsigned long long pack2(float lo, float hi) {
    unsigned long long r;
    asm("mov.b64 %0, {%1, %2};" : "=l"(r) : "f"(lo), "f"(hi));
    return r;
}
__device__ __forceinline__ float2 unpack2(unsigned long long v) {
    float2 r;
    asm("mov.b64 {%0, %1}, %2;" : "=f"(r.x), "=f"(r.y) : "l"(v));
    return r;
}

__device__ __forceinline__ float sigmoidf_(float x) {
    return 1.0f / (1.0f + __expf(-x));
}

// ===========================================================================
// Prep: pack weights gate-interleaved, pack biases, zero state
// ===========================================================================
__global__ void prep_kernel(const float* __restrict__ Wf, const float* __restrict__ Wi,
                            const float* __restrict__ Wc, const float* __restrict__ Wo,
                            const float* __restrict__ bf, const float* __restrict__ bi,
                            const float* __restrict__ bc, const float* __restrict__ bo) {
    int idx = blockIdx.x * blockDim.x + threadIdx.x;
    int stride = gridDim.x * blockDim.x;
    // Recurrent part: rows k in [0, U) of each W
    for (int i = idx; i < 1024 * 1024; i += stride) {
        int k = i >> 10, u = i & 1023;
        int s = k * 1024 + u;
        float4 v = make_float4(Wf[s], Wi[s], Wc[s], Wo[s]);
        *(float4*)&g_Whp[((size_t)k << 12) + (u << 2)] = v;
    }
    // Input part: rows U + d
    for (int i = idx; i < 512 * 1024; i += stride) {
        int d = i >> 10, u = i & 1023;
        int s = (1024 + d) * 1024 + u;
        float4 v = make_float4(Wf[s], Wi[s], Wc[s], Wo[s]);
        *(float4*)&g_Wxp[((size_t)d << 12) + (u << 2)] = v;
    }
    for (int u = idx; u < 1024; u += stride)
        *(float4*)&g_bp[u << 2] = make_float4(bf[u], bi[u], bc[u], bo[u]);
    for (int i = idx; i < BB * UU; i += stride) {
        g_h[0][i] = 0.0f;
        g_c[i] = 0.0f;
    }
}

// ===========================================================================
// zx GEMM:  zx[t][b][c] = bias[c] + sum_d x[b][t][d] * Wxp[d][c]
// rows r = t*32+b (M=16384), cols c (N=4096), K=512.  Tiles 64x64x32, 4x4/thread.
// ===========================================================================
#define ZBM 64
#define ZBN 64
#define ZBK 32
#define ZAPAD 68  // padded row length for As (multiple of 4 for LDS.128 alignment)

__global__ __launch_bounds__(256) void zx_kernel(const float* __restrict__ x) {
    __shared__ __align__(16) float As[ZBK][ZAPAD];  // [k][row]
    __shared__ __align__(16) float Bs[ZBK][ZBN];    // [k][col]

    int row0 = blockIdx.x * ZBM;
    int c0 = blockIdx.y * ZBN;
    int tid = threadIdx.x;
    int tx = tid & 15;        // col group: cols tx*4..tx*4+3
    int ty = tid >> 4;        // row group: rows ty*4..ty*4+3

    unsigned long long acc01[4], acc23[4];
#pragma unroll
    for (int r = 0; r < 4; r++) { acc01[r] = 0ull; acc23[r] = 0ull; }

    // staging thread maps
    int ar = tid >> 2, akq = tid & 3;   // As: row ar, k-quad akq
    int bkr = tid >> 3, bcq = tid & 7;  // Bs: k-row bkr, col-quad bcq

    for (int k0 = 0; k0 < DD; k0 += ZBK) {
        __syncthreads();
        // Stage As (transpose x tile into [k][row])
#pragma unroll
        for (int i = 0; i < 2; i++) {
            int koff = (akq + i * 4) * 4;
            int row = row0 + ar;
            int t = row >> 5, b = row & 31;
            float4 v = *(const float4*)&x[((size_t)b * TT + t) * DD + k0 + koff];
            As[koff + 0][ar] = v.x;
            As[koff + 1][ar] = v.y;
            As[koff + 2][ar] = v.z;
            As[koff + 3][ar] = v.w;
        }
        // Stage Bs
#pragma unroll
        for (int i = 0; i < 2; i++) {
            int coff = (bcq + i * 8) * 4;
            float4 v = *(const float4*)&g_Wxp[(size_t)(k0 + bkr) * NC + c0 + coff];
            *(float4*)&Bs[bkr][coff] = v;
        }
        __syncthreads();

#pragma unroll
        for (int kk = 0; kk < ZBK; kk++) {
            float4 a = *(const float4*)&As[kk][ty * 4];
            ulonglong2 bv = *(const ulonglong2*)&Bs[kk][tx * 4];
            unsigned long long a0 = pack2(a.x, a.x);
            unsigned long long a1 = pack2(a.y, a.y);
            unsigned long long a2 = pack2(a.z, a.z);
            unsigned long long a3 = pack2(a.w, a.w);
            fma2(acc01[0], a0, bv.x); fma2(acc23[0], a0, bv.y);
            fma2(acc01[1], a1, bv.x); fma2(acc23[1], a1, bv.y);
            fma2(acc01[2], a2, bv.x); fma2(acc23[2], a2, bv.y);
            fma2(acc01[3], a3, bv.x); fma2(acc23[3], a3, bv.y);
        }
    }

    float4 bias = *(const float4*)&g_bp[c0 + tx * 4];
#pragma unroll
    for (int r = 0; r < 4; r++) {
        float2 v01 = unpack2(acc01[r]);
        float2 v23 = unpack2(acc23[r]);
        float4 o;
        o.x = v01.x + bias.x;
        o.y = v01.y + bias.y;
        o.z = v23.x + bias.z;
        o.w = v23.y + bias.w;
        int row = row0 + ty * 4 + r;
        *(float4*)&g_zx[(size_t)row * NC + c0 + tx * 4] = o;
    }
}

// ===========================================================================
// Recurrent step: 128 CTAs x 8 units. z = h @ Wh (+ zx), then gate math.
// thread = (b = tid&31, uq = tid>>5): one unit's 4 gates for one batch.
// ===========================================================================
#define KC 128

__global__ __launch_bounds__(256) void step_kernel(float* __restrict__ out, int t) {
    __shared__ __align__(16) float hs[KC][33];  // [k][b]
    __shared__ __align__(16) float ws[KC][36];  // [k][32 cols], padded to mult-of-4

    const float* __restrict__ h_in = g_h[t & 1];
    float* __restrict__ h_out = g_h[(t + 1) & 1];

    int tid = threadIdx.x;
    int b = tid & 31;
    int uq = tid >> 5;         // warp id == unit-in-CTA (uniform per warp)
    int cu = blockIdx.x;       // unit chunk: units [cu*8, cu*8+8)

    unsigned long long acc_fi = 0ull, acc_go = 0ull;

    int hb = tid >> 3, hk = tid & 7;   // h staging map
    int wkr = tid >> 3, wcq = tid & 7; // w staging map

    for (int k0 = 0; k0 < UU; k0 += KC) {
        __syncthreads();
        // Stage h chunk [KC][32] (transposed)
#pragma unroll
        for (int i = 0; i < 4; i++) {
            int koff = (hk + i * 8) * 4;
            float4 v = *(const float4*)&h_in[hb * UU + k0 + koff];
            hs[koff + 0][hb] = v.x;
            hs[koff + 1][hb] = v.y;
            hs[koff + 2][hb] = v.z;
            hs[koff + 3][hb] = v.w;
        }
        // Stage weight chunk [KC][32]
#pragma unroll
        for (int i = 0; i < 4; i++) {
            int k = wkr + i * 32;
            float4 v = *(const float4*)&g_Whp[(size_t)(k0 + k) * NC + cu * 32 + wcq * 4];
            *(float4*)&ws[k][wcq * 4] = v;
        }
        __syncthreads();

#pragma unroll 16
        for (int kk = 0; kk < KC; kk++) {
            float h = hs[kk][b];
            unsigned long long hh = pack2(h, h);
            ulonglong2 wv = *(const ulonglong2*)&ws[kk][uq * 4];  // (wf,wi),(wg,wo)
            fma2(acc_fi, hh, wv.x);
            fma2(acc_go, hh, wv.y);
        }
    }

    // Gate math
    float2 fi = unpack2(acc_fi);
    float2 go = unpack2(acc_go);
    int unit = cu * 8 + uq;
    float4 zx4 = *(const float4*)&g_zx[((size_t)t * BB + b) * NC + cu * 32 + uq * 4];
    float zf = fi.x + zx4.x;
    float zi = fi.y + zx4.y;
    float zg = go.x + zx4.z;
    float zo = go.y + zx4.w;

    float f = sigmoidf_(zf);
    float ii = sigmoidf_(zi);
    float g = tanhf(zg);
    float o = sigmoidf_(zo);

    int ci = b * UU + unit;
    float c = f * g_c[ci] + ii * g;
    g_c[ci] = c;
    float h = o * tanhf(c);
    h_out[ci] = h;
    out[((size_t)b * TT + t) * UU + unit] = h;
}

// ===========================================================================
// Launch
// ===========================================================================
extern "C" void kernel_launch(void* const* d_in, const int* in_sizes, int n_in,
                              void* d_out, int out_size) {
    const float* data = (const float*)d_in[0];
    const float* Wf = (const float*)d_in[1];
    const float* bf = (const float*)d_in[2];
    const float* Wi = (const float*)d_in[3];
    const float* bi = (const float*)d_in[4];
    const float* Wc = (const float*)d_in[5];
    const float* bc = (const float*)d_in[6];
    const float* Wo = (const float*)d_in[7];
    const float* bo = (const float*)d_in[8];
    float* out = (float*)d_out;

    prep_kernel<<<512, 256>>>(Wf, Wi, Wc, Wo, bf, bi, bc, bo);

    dim3 zgrid(TT * BB / ZBM, NC / ZBN);  // (256, 64)
    zx_kernel<<<zgrid, 256>>>(data);

    for (int t = 0; t < TT; t++) {
        step_kernel<<<128, 256>>>(out, t);
    }
}

// round 2
// speedup vs baseline: 2.1863x; 2.1863x over previous
#include <cuda_runtime.h>
#include <math.h>
#include <stdint.h>

// Problem constants
#define BB 32
#define TT 512
#define DD 512
#define UU 1024
#define NC 4096   // 4*U packed gate columns, layout [unit][gate], gate order f,i,g,o

#define NCTA 128      // persistent CTAs (1 per SM, <=148 so all co-resident)
#define CU 32         // gate-cols per CTA (8 units)
#define NSLICE 16     // K-split factor
#define KSL 64        // k per slice (1024/16)

// -------- device scratch --------
__device__ float g_Whp[1024 * 4096];          // [k][u*4+g] recurrent weights (packed)
__device__ float g_Wxp[512 * 4096];           // [d][u*4+g] input weights (packed)
__device__ float g_bp[4096];                  // packed biases
__device__ float g_zx[(size_t)TT * BB * NC];  // [t][b][u*4+g]  x-part (+bias)
__device__ float g_hT[2][UU * BB];            // ping-pong hidden state, layout [u][b]
__device__ unsigned g_bar;                    // grid barrier counter

// -------- f32x2 helpers --------
__device__ __forceinline__ void fma2(unsigned long long& acc, unsigned long long a,
                                     unsigned long long b) {
    asm("fma.rn.f32x2 %0, %1, %2, %3;" : "=l"(acc) : "l"(a), "l"(b), "l"(acc));
}
__device__ __forceinline__ unsigned long long dup2(float x) {
    unsigned long long r;
    asm("mov.b64 %0, {%1, %1};" : "=l"(r) : "f"(x));
    return r;
}
__device__ __forceinline__ float2 unpack2(unsigned long long v) {
    float2 r;
    asm("mov.b64 {%0, %1}, %2;" : "=f"(r.x), "=f"(r.y) : "l"(v));
    return r;
}
__device__ __forceinline__ float sigmoidf_(float x) {
    return 1.0f / (1.0f + __expf(-x));
}

// ===========================================================================
// Prep: pack weights gate-interleaved, pack biases, zero h0 + barrier
// ===========================================================================
__global__ void prep_kernel(const float* __restrict__ Wf, const float* __restrict__ Wi,
                            const float* __restrict__ Wc, const float* __restrict__ Wo,
                            const float* __restrict__ bf, const float* __restrict__ bi,
                            const float* __restrict__ bc, const float* __restrict__ bo) {
    int idx = blockIdx.x * blockDim.x + threadIdx.x;
    int stride = gridDim.x * blockDim.x;
    if (idx == 0) g_bar = 0u;
    for (int i = idx; i < 1024 * 1024; i += stride) {
        int k = i >> 10, u = i & 1023;
        int s = k * 1024 + u;
        float4 v = make_float4(Wf[s], Wi[s], Wc[s], Wo[s]);
        *(float4*)&g_Whp[((size_t)k << 12) + (u << 2)] = v;
    }
    for (int i = idx; i < 512 * 1024; i += stride) {
        int d = i >> 10, u = i & 1023;
        int s = (1024 + d) * 1024 + u;
        float4 v = make_float4(Wf[s], Wi[s], Wc[s], Wo[s]);
        *(float4*)&g_Wxp[((size_t)d << 12) + (u << 2)] = v;
    }
    for (int u = idx; u < 1024; u += stride)
        *(float4*)&g_bp[u << 2] = make_float4(bf[u], bi[u], bc[u], bo[u]);
    for (int i = idx; i < UU * BB; i += stride) g_hT[0][i] = 0.0f;
}

// ===========================================================================
// zx GEMM:  zx[t][b][c] = bias[c] + sum_d x[b][t][d] * Wxp[d][c]
// ===========================================================================
#define ZBM 64
#define ZBN 64
#define ZBK 32
#define ZAPAD 68

__global__ __launch_bounds__(256) void zx_kernel(const float* __restrict__ x) {
    __shared__ __align__(16) float As[ZBK][ZAPAD];
    __shared__ __align__(16) float Bs[ZBK][ZBN];

    int row0 = blockIdx.x * ZBM;
    int c0 = blockIdx.y * ZBN;
    int tid = threadIdx.x;
    int tx = tid & 15;
    int ty = tid >> 4;

    unsigned long long acc01[4], acc23[4];
#pragma unroll
    for (int r = 0; r < 4; r++) { acc01[r] = 0ull; acc23[r] = 0ull; }

    int ar = tid >> 2, akq = tid & 3;
    int bkr = tid >> 3, bcq = tid & 7;

    for (int k0 = 0; k0 < DD; k0 += ZBK) {
        __syncthreads();
#pragma unroll
        for (int i = 0; i < 2; i++) {
            int koff = (akq + i * 4) * 4;
            int row = row0 + ar;
            int t = row >> 5, b = row & 31;
            float4 v = *(const float4*)&x[((size_t)b * TT + t) * DD + k0 + koff];
            As[koff + 0][ar] = v.x;
            As[koff + 1][ar] = v.y;
            As[koff + 2][ar] = v.z;
            As[koff + 3][ar] = v.w;
        }
#pragma unroll
        for (int i = 0; i < 2; i++) {
            int coff = (bcq + i * 8) * 4;
            float4 v = *(const float4*)&g_Wxp[(size_t)(k0 + bkr) * NC + c0 + coff];
            *(float4*)&Bs[bkr][coff] = v;
        }
        __syncthreads();

#pragma unroll
        for (int kk = 0; kk < ZBK; kk++) {
            float4 a = *(const float4*)&As[kk][ty * 4];
            ulonglong2 bv = *(const ulonglong2*)&Bs[kk][tx * 4];
            unsigned long long a0 = dup2(a.x);
            unsigned long long a1 = dup2(a.y);
            unsigned long long a2 = dup2(a.z);
            unsigned long long a3 = dup2(a.w);
            fma2(acc01[0], a0, bv.x); fma2(acc23[0], a0, bv.y);
            fma2(acc01[1], a1, bv.x); fma2(acc23[1], a1, bv.y);
            fma2(acc01[2], a2, bv.x); fma2(acc23[2], a2, bv.y);
            fma2(acc01[3], a3, bv.x); fma2(acc23[3], a3, bv.y);
        }
    }

    float4 bias = *(const float4*)&g_bp[c0 + tx * 4];
#pragma unroll
    for (int r = 0; r < 4; r++) {
        float2 v01 = unpack2(acc01[r]);
        float2 v23 = unpack2(acc23[r]);
        float4 o;
        o.x = v01.x + bias.x;
        o.y = v01.y + bias.y;
        o.z = v23.x + bias.z;
        o.w = v23.y + bias.w;
        int row = row0 + ty * 4 + r;
        *(float4*)&g_zx[(size_t)row * NC + c0 + tx * 4] = o;
    }
}

// ===========================================================================
// Persistent recurrent kernel: all 512 timesteps, grid barrier between steps.
// 128 CTAs x 256 threads. CTA cu owns gate-cols [32cu, 32cu+32) (units 8cu..8cu+7).
// Weights resident in smem (128 KB). K-split 16; partials reduced via smem.
// Cell state c lives in registers for the whole run.
// smem: ws[1024][32] floats (128KB) + red[16][16][32] float2 (64KB) = 192KB
// ===========================================================================
__global__ __launch_bounds__(256, 1) void lstm_persistent(float* __restrict__ out) {
    extern __shared__ __align__(16) float smem[];
    float* ws = smem;                                        // [k][32]  128KB
    unsigned long long* red = (unsigned long long*)(smem + 1024 * 32);  // [s][cp16][b32] f32x2

    const int tid = threadIdx.x;
    const int cu = blockIdx.x;

    // --- load this CTA's weight slice into smem (once) ---
    {
        const float4* src = (const float4*)(g_Whp + (size_t)cu * CU);
        float4* dst = (float4*)ws;
        // k rows: g_Whp row pitch = 4096 floats = 1024 float4; slice = 8 float4/row
        for (int i = tid; i < 1024 * 8; i += 256) {
            int k = i >> 3, q = i & 7;
            dst[k * 8 + q] = src[(size_t)k * 1024 + q];
        }
    }

    // --- thread roles ---
    const int s = tid >> 4;          // k-slice 0..15
    const int cov = tid & 15;
    const int bg = cov & 7;          // batch group
    const int cg = cov >> 3;         // col group (16 cols each)
    const int b0 = bg * 4;
    const int c0 = cg * 16;
    const int kb = s * KSL;

    const int up = tid >> 5;         // gate-math role: unit-in-CTA 0..7
    const int gb = tid & 31;         //                 batch 0..31

    float c_state = 0.0f;            // register-resident cell state for (up, gb)

    __syncthreads();                 // weights ready

    for (int t = 0; t < TT; t++) {
        const float* __restrict__ hT = g_hT[t & 1];
        float* __restrict__ hTo = g_hT[(t + 1) & 1];

        // ---- GEMM: acc[b][cp] over k in [kb, kb+64) ----
        unsigned long long acc[4][8];
#pragma unroll
        for (int b = 0; b < 4; b++)
#pragma unroll
            for (int p = 0; p < 8; p++) acc[b][p] = 0ull;

        const float4* hp = (const float4*)(hT + (size_t)kb * 32 + b0);  // stride 8 float4 per k
        const ulonglong2* wrow0 = (const ulonglong2*)(ws + kb * 32 + c0);

        float4 bufA[4], bufB[4];
#pragma unroll
        for (int j = 0; j < 4; j++) bufA[j] = __ldcg(hp + (size_t)j * 8);

#pragma unroll
        for (int kc = 0; kc < KSL; kc += 8) {
#pragma unroll
            for (int j = 0; j < 4; j++) bufB[j] = __ldcg(hp + (size_t)(kc + 4 + j) * 8);
#pragma unroll
            for (int j = 0; j < 4; j++) {
                float4 hv = bufA[j];
                unsigned long long h0 = dup2(hv.x), h1 = dup2(hv.y);
                unsigned long long h2 = dup2(hv.z), h3 = dup2(hv.w);
                const ulonglong2* wr = wrow0 + (size_t)(kc + j) * 8;  // row pitch 32 fl = 8 ull2... (32 floats = 128B = 8 ulonglong2)
#pragma unroll
                for (int q = 0; q < 4; q++) {
                    ulonglong2 w2 = wr[q];
                    fma2(acc[0][2 * q], h0, w2.x); fma2(acc[0][2 * q + 1], h0, w2.y);
                    fma2(acc[1][2 * q], h1, w2.x); fma2(acc[1][2 * q + 1], h1, w2.y);
                    fma2(acc[2][2 * q], h2, w2.x); fma2(acc[2][2 * q + 1], h2, w2.y);
                    fma2(acc[3][2 * q], h3, w2.x); fma2(acc[3][2 * q + 1], h3, w2.y);
                }
            }
            if (kc + 8 < KSL) {
#pragma unroll
                for (int j = 0; j < 4; j++) bufA[j] = __ldcg(hp + (size_t)(kc + 8 + j) * 8);
            }
#pragma unroll
            for (int j = 0; j < 4; j++) {
                float4 hv = bufB[j];
                unsigned long long h0 = dup2(hv.x), h1 = dup2(hv.y);
                unsigned long long h2 = dup2(hv.z), h3 = dup2(hv.w);
                const ulonglong2* wr = wrow0 + (size_t)(kc + 4 + j) * 8;
#pragma unroll
                for (int q = 0; q < 4; q++) {
                    ulonglong2 w2 = wr[q];
                    fma2(acc[0][2 * q], h0, w2.x); fma2(acc[0][2 * q + 1], h0, w2.y);
                    fma2(acc[1][2 * q], h1, w2.x); fma2(acc[1][2 * q + 1], h1, w2.y);
                    fma2(acc[2][2 * q], h2, w2.x); fma2(acc[2][2 * q + 1], h2, w2.y);
                    fma2(acc[3][2 * q], h3, w2.x); fma2(acc[3][2 * q + 1], h3, w2.y);
                }
            }
        }

        // ---- write partials: red[s][cp_global][b] ----
#pragma unroll
        for (int b = 0; b < 4; b++)
#pragma unroll
            for (int p = 0; p < 8; p++)
                red[((size_t)s * 16 + cg * 8 + p) * 32 + b0 + b] = acc[b][p];
        __syncthreads();

        // ---- reduce + gate math: thread = (unit up, batch gb) ----
        {
            float2 fi = make_float2(0.f, 0.f), go = make_float2(0.f, 0.f);
            const float2* red2 = (const float2*)red;
#pragma unroll
            for (int ss = 0; ss < NSLICE; ss++) {
                float2 a = red2[((size_t)ss * 16 + 2 * up) * 32 + gb];
                float2 bq = red2[((size_t)ss * 16 + 2 * up + 1) * 32 + gb];
                fi.x += a.x; fi.y += a.y;
                go.x += bq.x; go.y += bq.y;
            }
            int ug = cu * 8 + up;  // global unit
            float4 zx4 = *(const float4*)&g_zx[((size_t)t * BB + gb) * NC + ug * 4];
            float zf = fi.x + zx4.x;
            float zi = fi.y + zx4.y;
            float zg = go.x + zx4.z;
            float zo = go.y + zx4.w;

            float f = sigmoidf_(zf);
            float ii = sigmoidf_(zi);
            float g = tanhf(zg);
            float o = sigmoidf_(zo);
            c_state = f * c_state + ii * g;
            float h = o * tanhf(c_state);

            hTo[ug * 32 + gb] = h;
            out[((size_t)gb * TT + t) * UU + ug] = h;
        }

        // ---- grid barrier ----
        __threadfence();
        __syncthreads();
        if (tid == 0) {
            unsigned target = (unsigned)NCTA * (unsigned)(t + 1);
            atomicAdd(&g_bar, 1u);
            volatile unsigned* p = &g_bar;
            while (*p < target) {}
        }
        __syncthreads();
        __threadfence();
    }
}

// ===========================================================================
// Launch
// ===========================================================================
extern "C" void kernel_launch(void* const* d_in, const int* in_sizes, int n_in,
                              void* d_out, int out_size) {
    const float* data = (const float*)d_in[0];
    const float* Wf = (const float*)d_in[1];
    const float* bf = (const float*)d_in[2];
    const float* Wi = (const float*)d_in[3];
    const float* bi = (const float*)d_in[4];
    const float* Wc = (const float*)d_in[5];
    const float* bc = (const float*)d_in[6];
    const float* Wo = (const float*)d_in[7];
    const float* bo = (const float*)d_in[8];
    float* out = (float*)d_out;

    prep_kernel<<<512, 256>>>(Wf, Wi, Wc, Wo, bf, bi, bc, bo);

    dim3 zgrid(TT * BB / ZBM, NC / ZBN);
    zx_kernel<<<zgrid, 256>>>(data);

    static int smem_set = 0;
    const int smem_bytes = 1024 * 32 * 4 + 16 * 16 * 32 * 8;  // 128KB + 64KB
    if (!smem_set) {
        cudaFuncSetAttribute(lstm_persistent,
                             cudaFuncAttributeMaxDynamicSharedMemorySize, smem_bytes);
        smem_set = 1;
    }
    lstm_persistent<<<NCTA, 256, smem_bytes>>>(out);
}